// round 11
// baseline (speedup 1.0000x reference)
#include <cuda_runtime.h>
#include <cuda_fp16.h>
#include <cstdint>

// QuadraticConv2D implicit GEMM on fp16 mma.sync (f32 accumulate).
// out[m,o] = sum_{l,c} F_l[m,c] * W[l,c,o];  M=65536, K=54*64 (+exact bias), N=64.
// CTA: 256 thr, 256 m rows (4 image rows), warp tile m32n64, grid 256.
// x staged fp16 in smem (57KB, conflict-free stride-72).
// W fragment-packed in gmem; B fragments via coalesced LDG.128 (L1-resident).
// No W smem, no cp.async, no main-loop barriers.
// i-tap register cache (features grouped by i) cuts LDS ~45%; accumulators
// are bias-initialized (exact fp32 bias, reordered to the front).

#define XS_STRIDE 72                    // halfs per w position (conflict-free)
#define XS_ROW    (66 * XS_STRIDE)      // 4752 halfs per image row
#define XS_HALFS  (6 * XS_ROW)          // 28512
#define SMEM_BYTES (XS_HALFS * 2)       // 57024 B

// Fragment-packed weights: Wf[l][q][g2][lane] -> uint4 =
//   { b0(nt=2g2), b1(2g2), b0(2g2+1), b1(2g2+1) } for that lane.
__device__ __align__(16) uint4 Wfg[54 * 16 * 32];
__device__ float bvecg[64];             // exact bias contribution (fp32)

__constant__ unsigned char F_I[54] = {
    0,0,0,0,0,0,0,0,0,0, 1,1,1,1,1,1,1,1,1, 2,2,2,2,2,2,2,2,
    3,3,3,3,3,3,3, 4,4,4,4,4,4, 5,5,5,5,5, 6,6,6,6, 7,7,7, 8,8};
__constant__ unsigned char F_J[54] = {
    0,1,2,3,4,5,6,7,8,255, 1,2,3,4,5,6,7,8,255, 2,3,4,5,6,7,8,255,
    3,4,5,6,7,8,255, 4,5,6,7,8,255, 5,6,7,8,255, 6,7,8,255, 7,8,255, 8,255};
__constant__ unsigned char F_L[54] = {
    0,1,2,3,4,5,6,7,8,45, 9,10,11,12,13,14,15,16,46, 17,18,19,20,21,22,23,47,
    24,25,26,27,28,29,48, 30,31,32,33,34,49, 35,36,37,38,50,
    39,40,41,51, 42,43,52, 44,53};

static __device__ __forceinline__ void mma16816(float* d,
    uint32_t a0, uint32_t a1, uint32_t a2, uint32_t a3,
    uint32_t b0, uint32_t b1) {
    asm volatile(
        "mma.sync.aligned.m16n8k16.row.col.f32.f16.f16.f32 "
        "{%0,%1,%2,%3}, {%4,%5,%6,%7}, {%8,%9}, {%0,%1,%2,%3};"
        : "+f"(d[0]), "+f"(d[1]), "+f"(d[2]), "+f"(d[3])
        : "r"(a0), "r"(a1), "r"(a2), "r"(a3), "r"(b0), "r"(b1));
}
static __device__ __forceinline__ uint32_t lds32(uint32_t addr) {
    uint32_t v;
    asm volatile("ld.shared.b32 %0, [%1];" : "=r"(v) : "r"(addr));
    return v;
}
static __device__ __forceinline__ uint32_t packh2(float a, float b) {
    const __half2 h = __floats2half2_rn(a, b);
    return *(const uint32_t*)&h;
}

// ---- prep: fragment-pack W into Wfg; exact fp32 bias column sums ----
__global__ void prep_W(const float* __restrict__ wk) {
    const int l = blockIdx.x;
    if (l < 54) {
        const int tid = threadIdx.x;          // 512 threads = 16 frag-groups x 32
        const int q    = tid >> 7;
        const int g2   = (tid >> 5) & 3;
        const int lane = tid & 31;
        const int r = lane >> 2, t4 = lane & 3;
        const int n0 = (2 * g2) * 8 + r;
        const int n1 = (2 * g2 + 1) * 8 + r;
        const int k0 = 16 * q + 2 * t4;
        const float* w = wk + l * 4096;
        uint4 v;
        v.x = packh2(w[(k0    ) * 64 + n0], w[(k0 + 1) * 64 + n0]);
        v.y = packh2(w[(k0 + 8) * 64 + n0], w[(k0 + 9) * 64 + n0]);
        v.z = packh2(w[(k0    ) * 64 + n1], w[(k0 + 1) * 64 + n1]);
        v.w = packh2(w[(k0 + 8) * 64 + n1], w[(k0 + 9) * 64 + n1]);
        Wfg[(l * 16 + q * 4 + g2) * 32 + lane] = v;
    } else if (threadIdx.x < 64) {
        float s = 0.f;
        for (int c = 0; c < 64; ++c) s += wk[54 * 4096 + c * 64 + threadIdx.x];
        bvecg[threadIdx.x] = s;
    }
}

// --------------------------------- main -------------------------------------
__global__ __launch_bounds__(256, 2)
void qconv_mma(const float* __restrict__ x, float* __restrict__ out) {
    extern __shared__ __half xsm[];
    __half* xs = xsm;
    const uint32_t sb = (uint32_t)__cvta_generic_to_shared(xsm);

    const int t    = threadIdx.x;
    const int warp = t >> 5, lane = t & 31;
    const int r    = lane >> 2, t4 = lane & 3;
    const int irow  = warp >> 1;          // image row within CTA (0..3)
    const int wbase = (warp & 1) * 32;    // w offset within image row
    const int bb = blockIdx.x >> 4;
    const int r0 = (blockIdx.x & 15) * 4;

    // ---- stage 6 x-rows as fp16 (stride-72, zero halo) ----
    #pragma unroll
    for (int rr = 0; rr < 6; ++rr) {
        const int hh = r0 + rr - 1;
        const bool ok = (hh >= 0 && hh < 64);
        const float4* src =
            (const float4*)(x + (size_t)(bb * 64 + (ok ? hh : 0)) * 4096);
        #pragma unroll
        for (int k = 0; k < 4; ++k) {
            const int idx = t + k * 256;          // float4 idx 0..1023
            const int ww = idx >> 4, c4 = idx & 15;
            const float4 v = ok ? src[idx] : make_float4(0.f, 0.f, 0.f, 0.f);
            uint2 pk;
            pk.x = packh2(v.x, v.y);
            pk.y = packh2(v.z, v.w);
            *(uint2*)(xs + rr * XS_ROW + (ww + 1) * XS_STRIDE + c4 * 4) = pk;
        }
    }
    if (t < 192) {
        const int rr = t >> 5, side = (t >> 4) & 1, c4 = t & 15;
        *(uint2*)(xs + rr * XS_ROW + (side ? 65 : 0) * XS_STRIDE + c4 * 4) =
            make_uint2(0u, 0u);
    }
    __syncthreads();          // the ONLY barrier

    // ---- accumulators, bias-initialized (exact fp32 bias, reordered) ----
    float acc[2][8][4];
    #pragma unroll
    for (int b = 0; b < 8; ++b) {
        const int n = b * 8 + t4 * 2;
        const float bvx = bvecg[n], bvy = bvecg[n + 1];
        #pragma unroll
        for (int a = 0; a < 2; ++a) {
            acc[a][b][0] = bvx; acc[a][b][1] = bvy;
            acc[a][b][2] = bvx; acc[a][b][3] = bvy;
        }
    }

    uint32_t xi[4][8];                    // i-tap cache: 4 m8-rows x (4q x 2)
    int cur_i = -1;

    for (int f = 0; f < 54; ++f) {
        const int ii = F_I[f], jj = F_J[f];
        const bool quad = (jj != 255);

        if (ii != cur_i) {                // reload i-tap cache (~10x total)
            cur_i = ii;
            const int di = ii / 3, dj = ii % 3;
            #pragma unroll
            for (int mi = 0; mi < 4; ++mi) {
                const uint32_t base = sb
                    + ((irow + di) * XS_ROW
                       + (wbase + mi * 8 + r + dj) * XS_STRIDE) * 2 + t4 * 4;
                #pragma unroll
                for (int q = 0; q < 4; ++q) {
                    xi[mi][2 * q]     = lds32(base + q * 32);
                    xi[mi][2 * q + 1] = lds32(base + q * 32 + 16);
                }
            }
        }

        uint32_t jb[4];
        if (quad) {
            const int dr = jj / 3, dc = jj % 3;
            #pragma unroll
            for (int mi = 0; mi < 4; ++mi)
                jb[mi] = sb + ((irow + dr) * XS_ROW
                               + (wbase + mi * 8 + r + dc) * XS_STRIDE) * 2
                       + t4 * 4;
        }

        const uint4* wf = Wfg + (size_t)(F_L[f] * 16) * 32 + lane;

        #pragma unroll
        for (int q = 0; q < 4; ++q) {
            uint32_t ha[4][2];
            #pragma unroll
            for (int mi = 0; mi < 4; ++mi) {
                if (quad) {
                    const uint32_t w0 = lds32(jb[mi] + q * 32);
                    const uint32_t w1 = lds32(jb[mi] + q * 32 + 16);
                    const __half2 p0 =
                        __hmul2(*(const __half2*)&xi[mi][2 * q],
                                *(const __half2*)&w0);
                    const __half2 p1 =
                        __hmul2(*(const __half2*)&xi[mi][2 * q + 1],
                                *(const __half2*)&w1);
                    ha[mi][0] = *(const uint32_t*)&p0;
                    ha[mi][1] = *(const uint32_t*)&p1;
                } else {
                    ha[mi][0] = xi[mi][2 * q];
                    ha[mi][1] = xi[mi][2 * q + 1];
                }
            }

            #pragma unroll
            for (int g2 = 0; g2 < 4; ++g2) {
                const uint4 bv = __ldg(wf + (q * 4 + g2) * 32);
                mma16816(acc[0][2 * g2],     ha[0][0], ha[1][0], ha[0][1],
                         ha[1][1], bv.x, bv.y);
                mma16816(acc[0][2 * g2 + 1], ha[0][0], ha[1][0], ha[0][1],
                         ha[1][1], bv.z, bv.w);
                mma16816(acc[1][2 * g2],     ha[2][0], ha[3][0], ha[2][1],
                         ha[3][1], bv.x, bv.y);
                mma16816(acc[1][2 * g2 + 1], ha[2][0], ha[3][0], ha[2][1],
                         ha[3][1], bv.z, bv.w);
            }
        }
    }

    // ---- epilogue: float2 stores (bias already in accumulators) ----
    const int mrow0 = blockIdx.x * 256 + warp * 32 + r;
    #pragma unroll
    for (int mb = 0; mb < 2; ++mb) {
        #pragma unroll
        for (int nt = 0; nt < 8; ++nt) {
            const int n = nt * 8 + t4 * 2;
            float* o0 = out + (size_t)(mrow0 + mb * 16) * 64 + n;
            *(float2*)o0 = make_float2(acc[mb][nt][0], acc[mb][nt][1]);
            *(float2*)(o0 + 8 * 64) = make_float2(acc[mb][nt][2], acc[mb][nt][3]);
        }
    }
}

extern "C" void kernel_launch(void* const* d_in, const int* in_sizes, int n_in,
                              void* d_out, int out_size) {
    const float* x  = (const float*)d_in[0];
    const float* wk = (const float*)d_in[1];   // [55,64,64] (l,c,o) contiguous
    float* out = (float*)d_out;

    prep_W<<<55, 512>>>(wk);
    cudaFuncSetAttribute(qconv_mma,
                         cudaFuncAttributeMaxDynamicSharedMemorySize, SMEM_BYTES);
    qconv_mma<<<256, 256, SMEM_BYTES>>>(x, out);
}

// round 12
// speedup vs baseline: 1.0312x; 1.0312x over previous
#include <cuda_runtime.h>
#include <cuda_fp16.h>
#include <cstdint>

// QuadraticConv2D implicit GEMM on fp16 mma.sync (f32 accumulate).
// out[m,o] = sum_{l,c} F_l[m,c] * W[l,c,o];  M=65536, K=54*64 (+exact bias), N=64.
// CTA: 256 thr, 256 m rows (4 image rows), warp tile m32n64, grid 256.
// x staged fp16 in smem (57KB, conflict-free stride-72).
// W fragment-packed in gmem; B fragments via coalesced LDG.128 (L1-resident).
// A-fragment build SOFTWARE-PIPELINED one q-step ahead (ping-pong ha), incl.
// across feature boundaries -> LDS latency hidden under the MMA batches.

#define XS_STRIDE 72                    // halfs per w position (conflict-free)
#define XS_ROW    (66 * XS_STRIDE)      // 4752 halfs per image row
#define XS_HALFS  (6 * XS_ROW)          // 28512
#define SMEM_BYTES (XS_HALFS * 2)       // 57024 B

// Fragment-packed weights: Wf[l][q][g2][lane] -> uint4 =
//   { b0(nt=2g2), b1(2g2), b0(2g2+1), b1(2g2+1) } for that lane.
__device__ __align__(16) uint4 Wfg[54 * 16 * 32];
__device__ float bvecg[64];             // exact bias contribution (fp32)

__constant__ unsigned char F_I[54] = {
    0,0,0,0,0,0,0,0,0,0, 1,1,1,1,1,1,1,1,1, 2,2,2,2,2,2,2,2,
    3,3,3,3,3,3,3, 4,4,4,4,4,4, 5,5,5,5,5, 6,6,6,6, 7,7,7, 8,8};
__constant__ unsigned char F_J[54] = {
    0,1,2,3,4,5,6,7,8,255, 1,2,3,4,5,6,7,8,255, 2,3,4,5,6,7,8,255,
    3,4,5,6,7,8,255, 4,5,6,7,8,255, 5,6,7,8,255, 6,7,8,255, 7,8,255, 8,255};
__constant__ unsigned char F_L[54] = {
    0,1,2,3,4,5,6,7,8,45, 9,10,11,12,13,14,15,16,46, 17,18,19,20,21,22,23,47,
    24,25,26,27,28,29,48, 30,31,32,33,34,49, 35,36,37,38,50,
    39,40,41,51, 42,43,52, 44,53};

static __device__ __forceinline__ void mma16816(float* d,
    uint32_t a0, uint32_t a1, uint32_t a2, uint32_t a3,
    uint32_t b0, uint32_t b1) {
    asm volatile(
        "mma.sync.aligned.m16n8k16.row.col.f32.f16.f16.f32 "
        "{%0,%1,%2,%3}, {%4,%5,%6,%7}, {%8,%9}, {%0,%1,%2,%3};"
        : "+f"(d[0]), "+f"(d[1]), "+f"(d[2]), "+f"(d[3])
        : "r"(a0), "r"(a1), "r"(a2), "r"(a3), "r"(b0), "r"(b1));
}
static __device__ __forceinline__ uint32_t lds32(uint32_t addr) {
    uint32_t v;
    asm volatile("ld.shared.b32 %0, [%1];" : "=r"(v) : "r"(addr));
    return v;
}
static __device__ __forceinline__ uint32_t packh2(float a, float b) {
    const __half2 h = __floats2half2_rn(a, b);
    return *(const uint32_t*)&h;
}

// ---- prep: fragment-pack W into Wfg; exact fp32 bias column sums ----
__global__ void prep_W(const float* __restrict__ wk) {
    const int l = blockIdx.x;
    if (l < 54) {
        const int tid = threadIdx.x;          // 512 threads = 16 frag-groups x 32
        const int q    = tid >> 7;
        const int g2   = (tid >> 5) & 3;
        const int lane = tid & 31;
        const int r = lane >> 2, t4 = lane & 3;
        const int n0 = (2 * g2) * 8 + r;
        const int n1 = (2 * g2 + 1) * 8 + r;
        const int k0 = 16 * q + 2 * t4;
        const float* w = wk + l * 4096;
        uint4 v;
        v.x = packh2(w[(k0    ) * 64 + n0], w[(k0 + 1) * 64 + n0]);
        v.y = packh2(w[(k0 + 8) * 64 + n0], w[(k0 + 9) * 64 + n0]);
        v.z = packh2(w[(k0    ) * 64 + n1], w[(k0 + 1) * 64 + n1]);
        v.w = packh2(w[(k0 + 8) * 64 + n1], w[(k0 + 9) * 64 + n1]);
        Wfg[(l * 16 + q * 4 + g2) * 32 + lane] = v;
    } else if (threadIdx.x < 64) {
        float s = 0.f;
        for (int c = 0; c < 64; ++c) s += wk[54 * 4096 + c * 64 + threadIdx.x];
        bvecg[threadIdx.x] = s;
    }
}

// build the 4 A-fragments (one q-step) from tap addresses
static __device__ __forceinline__ void build_ha(uint32_t (*dst)[2],
                                                const uint32_t* ib,
                                                const uint32_t* jb,
                                                int q, bool quad) {
    #pragma unroll
    for (int mi = 0; mi < 4; ++mi) {
        uint32_t v0 = lds32(ib[mi] + q * 32);
        uint32_t v1 = lds32(ib[mi] + q * 32 + 16);
        if (quad) {
            const uint32_t w0 = lds32(jb[mi] + q * 32);
            const uint32_t w1 = lds32(jb[mi] + q * 32 + 16);
            const __half2 p0 = __hmul2(*(const __half2*)&v0,
                                       *(const __half2*)&w0);
            const __half2 p1 = __hmul2(*(const __half2*)&v1,
                                       *(const __half2*)&w1);
            v0 = *(const uint32_t*)&p0;
            v1 = *(const uint32_t*)&p1;
        }
        dst[mi][0] = v0;
        dst[mi][1] = v1;
    }
}

static __device__ __forceinline__ void mk_addrs(uint32_t sb, int irow, int wbase,
                                                int r, int t4, int ii, int jj,
                                                uint32_t* ib, uint32_t* jb,
                                                bool& quad) {
    const int di = ii / 3, dj = ii % 3;
    quad = (jj != 255);
    const int dr = quad ? jj / 3 : di, dc = quad ? jj % 3 : dj;
    #pragma unroll
    for (int mi = 0; mi < 4; ++mi) {
        const int wp = wbase + mi * 8 + r;
        ib[mi] = sb + ((irow + di) * XS_ROW + (wp + dj) * XS_STRIDE) * 2 + t4 * 4;
        jb[mi] = sb + ((irow + dr) * XS_ROW + (wp + dc) * XS_STRIDE) * 2 + t4 * 4;
    }
}

// --------------------------------- main -------------------------------------
__global__ __launch_bounds__(256, 2)
void qconv_mma(const float* __restrict__ x, float* __restrict__ out) {
    extern __shared__ __half xsm[];
    __half* xs = xsm;
    const uint32_t sb = (uint32_t)__cvta_generic_to_shared(xsm);

    const int t    = threadIdx.x;
    const int warp = t >> 5, lane = t & 31;
    const int r    = lane >> 2, t4 = lane & 3;
    const int irow  = warp >> 1;          // image row within CTA (0..3)
    const int wbase = (warp & 1) * 32;    // w offset within image row
    const int bb = blockIdx.x >> 4;
    const int r0 = (blockIdx.x & 15) * 4;

    // ---- stage 6 x-rows as fp16 (stride-72, zero halo) ----
    #pragma unroll
    for (int rr = 0; rr < 6; ++rr) {
        const int hh = r0 + rr - 1;
        const bool ok = (hh >= 0 && hh < 64);
        const float4* src =
            (const float4*)(x + (size_t)(bb * 64 + (ok ? hh : 0)) * 4096);
        #pragma unroll
        for (int k = 0; k < 4; ++k) {
            const int idx = t + k * 256;          // float4 idx 0..1023
            const int ww = idx >> 4, c4 = idx & 15;
            const float4 v = ok ? src[idx] : make_float4(0.f, 0.f, 0.f, 0.f);
            uint2 pk;
            pk.x = packh2(v.x, v.y);
            pk.y = packh2(v.z, v.w);
            *(uint2*)(xs + rr * XS_ROW + (ww + 1) * XS_STRIDE + c4 * 4) = pk;
        }
    }
    if (t < 192) {
        const int rr = t >> 5, side = (t >> 4) & 1, c4 = t & 15;
        *(uint2*)(xs + rr * XS_ROW + (side ? 65 : 0) * XS_STRIDE + c4 * 4) =
            make_uint2(0u, 0u);
    }
    __syncthreads();          // the ONLY barrier

    float acc[2][8][4];
    #pragma unroll
    for (int a = 0; a < 2; ++a)
        #pragma unroll
        for (int b = 0; b < 8; ++b)
            #pragma unroll
            for (int cc = 0; cc < 4; ++cc) acc[a][b][cc] = 0.f;

    uint32_t ib[4], jb[4], ibn[4], jbn[4];
    bool quad, quadn;
    mk_addrs(sb, irow, wbase, r, t4, F_I[0], F_J[0], ib, jb, quad);

    uint32_t ha[2][4][2];                 // ping-pong A fragments
    build_ha(ha[0], ib, jb, 0, quad);

    for (int f = 0; f < 54; ++f) {
        const uint4* wf = Wfg + (size_t)(F_L[f] * 16) * 32 + lane;
        const int fn = (f + 1 < 54) ? f + 1 : f;
        mk_addrs(sb, irow, wbase, r, t4, F_I[fn], F_J[fn], ibn, jbn, quadn);

        #pragma unroll
        for (int q = 0; q < 4; ++q) {
            // B fragments for this q (L1-resident, ~40 instr before first use)
            uint4 bv[4];
            #pragma unroll
            for (int g2 = 0; g2 < 4; ++g2)
                bv[g2] = __ldg(wf + (q * 4 + g2) * 32);

            // pipeline: build NEXT step's A fragments before issuing MMAs
            if (q < 3) build_ha(ha[(q + 1) & 1], ib, jb, q + 1, quad);
            else       build_ha(ha[0], ibn, jbn, 0, quadn);

            const uint32_t (*hc)[2] = ha[q & 1];
            #pragma unroll
            for (int g2 = 0; g2 < 4; ++g2) {
                mma16816(acc[0][2 * g2],     hc[0][0], hc[1][0], hc[0][1],
                         hc[1][1], bv[g2].x, bv[g2].y);
                mma16816(acc[0][2 * g2 + 1], hc[0][0], hc[1][0], hc[0][1],
                         hc[1][1], bv[g2].z, bv[g2].w);
                mma16816(acc[1][2 * g2],     hc[2][0], hc[3][0], hc[2][1],
                         hc[3][1], bv[g2].x, bv[g2].y);
                mma16816(acc[1][2 * g2 + 1], hc[2][0], hc[3][0], hc[2][1],
                         hc[3][1], bv[g2].z, bv[g2].w);
            }
        }

        #pragma unroll
        for (int mi = 0; mi < 4; ++mi) { ib[mi] = ibn[mi]; jb[mi] = jbn[mi]; }
        quad = quadn;
    }

    // ---- epilogue: exact bias add + float2 stores ----
    const int mrow0 = blockIdx.x * 256 + warp * 32 + r;
    #pragma unroll
    for (int mb = 0; mb < 2; ++mb) {
        #pragma unroll
        for (int nt = 0; nt < 8; ++nt) {
            const int n = nt * 8 + t4 * 2;
            const float bvx = bvecg[n], bvy = bvecg[n + 1];
            float* o0 = out + (size_t)(mrow0 + mb * 16) * 64 + n;
            *(float2*)o0 = make_float2(acc[mb][nt][0] + bvx, acc[mb][nt][1] + bvy);
            *(float2*)(o0 + 8 * 64) =
                make_float2(acc[mb][nt][2] + bvx, acc[mb][nt][3] + bvy);
        }
    }
}

extern "C" void kernel_launch(void* const* d_in, const int* in_sizes, int n_in,
                              void* d_out, int out_size) {
    const float* x  = (const float*)d_in[0];
    const float* wk = (const float*)d_in[1];   // [55,64,64] (l,c,o) contiguous
    float* out = (float*)d_out;

    prep_W<<<55, 512>>>(wk);
    cudaFuncSetAttribute(qconv_mma,
                         cudaFuncAttributeMaxDynamicSharedMemorySize, SMEM_BYTES);
    qconv_mma<<<256, 256, SMEM_BYTES>>>(x, out);
}